// round 2
// baseline (speedup 1.0000x reference)
#include <cuda_runtime.h>
#include <cuda_bf16.h>
#include <cstdint>

// ============================================================================
// ContrastiveLoss: sim = E E^T / 0.5 ; loss_i = -(log pos_sum - log all_sum)
// N = 16384, D = 128, labels in [0,64). Output: scalar mean over valid rows.
//
//   K0z: zero label histogram + detect label dtype (int32 vs int64)
//   K0 : fp32 -> bf16 conversion; A-copy pre-scaled by 2*log2(e); histogram
//   K1 : 128 CTAs x 8 warps; A fragments register-resident; 256 chunks of 64
//        cols (double-buffered cp.async); mma.m16n8k16 bf16->fp32; fused
//        epilogue: e = ex2(acc); all += e; if (label match) pos += e
//        (diagonal kept in, subtracted in K2)
//   K2 : per-row: subtract exp2(self-dot), loss_i, block reduce
//   K3 : final reduce -> d_out[0]
// ============================================================================

#define NMAX 16384
#define DIM  128
#define BM   128
#define BN   64
#define LDSB 136                // padded bf16 row stride (272 B)
#define EXP_SCALE 2.8853900817779268f   // 2 * log2(e)  (T = 0.5)

__device__ __nv_bfloat16 g_As[NMAX * DIM];   // scaled copy (A operand)
__device__ __nv_bfloat16 g_Bb[NMAX * DIM];   // unscaled copy (B operand)
__device__ unsigned char g_lab[NMAX];
__device__ int           g_cnt[64];
__device__ int           g_is64;
__device__ float         g_pos[NMAX];
__device__ float         g_all[NMAX];
__device__ float         g_bsum[256];
__device__ int           g_bcnt[256];

// ---------------------------------------------------------------- helpers ---
__device__ __forceinline__ unsigned smem_u32(const void* p) {
    return (unsigned)__cvta_generic_to_shared(p);
}
__device__ __forceinline__ void cp16(unsigned dst, const void* src) {
    asm volatile("cp.async.cg.shared.global [%0], [%1], 16;\n" :: "r"(dst), "l"(src));
}
__device__ __forceinline__ void cp_commit() {
    asm volatile("cp.async.commit_group;\n");
}
template <int N>
__device__ __forceinline__ void cp_wait() {
    asm volatile("cp.async.wait_group %0;\n" :: "n"(N));
}
__device__ __forceinline__ void ldm4(unsigned addr, unsigned& r0, unsigned& r1,
                                     unsigned& r2, unsigned& r3) {
    asm volatile("ldmatrix.sync.aligned.m8n8.x4.shared.b16 {%0,%1,%2,%3}, [%4];\n"
                 : "=r"(r0), "=r"(r1), "=r"(r2), "=r"(r3) : "r"(addr));
}
__device__ __forceinline__ void mma16816(float& c0, float& c1, float& c2, float& c3,
                                         unsigned a0, unsigned a1, unsigned a2, unsigned a3,
                                         unsigned b0, unsigned b1) {
    asm volatile("mma.sync.aligned.m16n8k16.row.col.f32.bf16.bf16.f32 "
                 "{%0,%1,%2,%3},{%4,%5,%6,%7},{%8,%9},{%0,%1,%2,%3};\n"
                 : "+f"(c0), "+f"(c1), "+f"(c2), "+f"(c3)
                 : "r"(a0), "r"(a1), "r"(a2), "r"(a3), "r"(b0), "r"(b1));
}
__device__ __forceinline__ float ex2f(float x) {
    float y;
    asm("ex2.approx.f32 %0, %1;\n" : "=f"(y) : "f"(x));
    return y;
}

// ------------------------------------------------------------------ K0z -----
// Zero histogram + sniff label dtype. If the buffer is int64 (values < 64),
// the odd 32-bit words of the first 64 elements are all zero. If it is int32,
// those words are 64 random labels in [0,64) — all-zero has P ~ 64^-64.
__global__ void k_zero(const int* __restrict__ labw) {
    if (threadIdx.x == 0) {
        int odd_or = 0;
        for (int i = 0; i < 64; ++i) odd_or |= labw[2 * i + 1];
        g_is64 = (odd_or == 0) ? 1 : 0;
    }
    if (threadIdx.x < 64) g_cnt[threadIdx.x] = 0;
}

// ------------------------------------------------------------------ K0 ------
__global__ void k_convert(const float* __restrict__ emb,
                          const void* __restrict__ lab, int n) {
    int row = blockIdx.x * blockDim.x + threadIdx.x;
    if (row >= n) return;
    const float4* src = (const float4*)(emb + (size_t)row * DIM);
    __nv_bfloat162* dA = (__nv_bfloat162*)(g_As + (size_t)row * DIM);
    __nv_bfloat162* dB = (__nv_bfloat162*)(g_Bb + (size_t)row * DIM);
#pragma unroll
    for (int i = 0; i < DIM / 4; ++i) {
        float4 v = src[i];
        dA[2 * i]     = __floats2bfloat162_rn(v.x * EXP_SCALE, v.y * EXP_SCALE);
        dA[2 * i + 1] = __floats2bfloat162_rn(v.z * EXP_SCALE, v.w * EXP_SCALE);
        dB[2 * i]     = __floats2bfloat162_rn(v.x, v.y);
        dB[2 * i + 1] = __floats2bfloat162_rn(v.z, v.w);
    }
    int lb = g_is64 ? (int)((const long long*)lab)[row]
                    : ((const int*)lab)[row];
    g_lab[row] = (unsigned char)lb;
    atomicAdd(&g_cnt[lb & 63], 1);
}

// ------------------------------------------------------------------ K1 ------
__global__ __launch_bounds__(256, 1) void k_main(int n) {
    __shared__ __align__(16) __nv_bfloat16 sB[2][BN * LDSB];
    __shared__ __align__(16) unsigned char sLab[2][BN];

    const int tid  = threadIdx.x;
    const int lane = tid & 31;
    const int wid  = tid >> 5;        // 0..7, owns rows [wid*16, wid*16+16)
    const int g    = lane >> 2;       // 0..7
    const int t    = lane & 3;        // 0..3
    const int nch  = n / BN;

    // ---- stage A tile (128 rows) into the two B buffers, pull to registers
    {
        const __nv_bfloat16* gA = g_As + (size_t)(blockIdx.x * BM) * DIM;
#pragma unroll
        for (int k = 0; k < 8; ++k) {
            int s = tid + k * 256;            // 0..2047 segments of 16 B
            int row = s >> 4, seg = s & 15;
            int half = row >> 6, lrow = row & 63;
            cp16(smem_u32(&sB[half][lrow * LDSB + seg * 8]), gA + row * DIM + seg * 8);
        }
        cp_commit();
        cp_wait<0>();
        __syncthreads();
    }

    unsigned af[8][4];                 // A fragments for the full K=128
    {
        int half   = wid >> 2;
        int lrbase = (wid & 3) * 16;
        int arow   = lrbase + (lane & 15);
        int acolo  = (lane >> 4) * 8;
#pragma unroll
        for (int kt = 0; kt < 8; ++kt) {
            unsigned addr = smem_u32(&sB[half][arow * LDSB + kt * 16 + acolo]);
            ldm4(addr, af[kt][0], af[kt][1], af[kt][2], af[kt][3]);
        }
    }
    __syncthreads();

    const int rb = blockIdx.x * BM + wid * 16;
    const unsigned lr0 = g_lab[rb + g];
    const unsigned lr1 = g_lab[rb + g + 8];

    float all0 = 0.f, all1 = 0.f, pos0 = 0.f, pos1 = 0.f;

    const int brow_off = (lane & 7) + ((lane >> 4) << 3);
    const int bcol_off = ((lane >> 3) & 1) * 8;

    auto load_chunk = [&](int c, int buf) {
        const __nv_bfloat16* gB = g_Bb + (size_t)(c * BN) * DIM;
#pragma unroll
        for (int k = 0; k < 4; ++k) {
            int s = tid + k * 256;            // 0..1023 segments of 16 B
            int row = s >> 4, seg = s & 15;
            cp16(smem_u32(&sB[buf][row * LDSB + seg * 8]), gB + row * DIM + seg * 8);
        }
        if (tid < 4)
            cp16(smem_u32(&sLab[buf][tid * 16]), g_lab + c * BN + tid * 16);
        cp_commit();
    };

    load_chunk(0, 0);
    if (nch > 1) load_chunk(1, 1);

    for (int c = 0; c < nch; ++c) {
        const int buf = c & 1;
        if (c + 1 == nch) cp_wait<0>(); else cp_wait<1>();
        __syncthreads();

        float acc[8][4];
#pragma unroll
        for (int i = 0; i < 8; ++i)
#pragma unroll
            for (int j = 0; j < 4; ++j) acc[i][j] = 0.f;

#pragma unroll
        for (int np = 0; np < 4; ++np) {
#pragma unroll
            for (int kt = 0; kt < 8; ++kt) {
                unsigned b0, b1, b2, b3;
                unsigned addr = smem_u32(
                    &sB[buf][(np * 16 + brow_off) * LDSB + kt * 16 + bcol_off]);
                ldm4(addr, b0, b1, b2, b3);
                mma16816(acc[2 * np][0], acc[2 * np][1], acc[2 * np][2], acc[2 * np][3],
                         af[kt][0], af[kt][1], af[kt][2], af[kt][3], b0, b1);
                mma16816(acc[2 * np + 1][0], acc[2 * np + 1][1],
                         acc[2 * np + 1][2], acc[2 * np + 1][3],
                         af[kt][0], af[kt][1], af[kt][2], af[kt][3], b2, b3);
            }
        }

        // fused epilogue: exp2 + masked accumulation (diagonal stays in; K2 fixes)
#pragma unroll
        for (int nt = 0; nt < 8; ++nt) {
            unsigned short pr = *(const unsigned short*)&sLab[buf][nt * 8 + 2 * t];
            unsigned l0 = pr & 0xFFu, l1 = pr >> 8;
            float e00 = ex2f(acc[nt][0]);
            float e01 = ex2f(acc[nt][1]);
            float e10 = ex2f(acc[nt][2]);
            float e11 = ex2f(acc[nt][3]);
            all0 += e00 + e01;
            all1 += e10 + e11;
            if (l0 == lr0) pos0 += e00;
            if (l1 == lr0) pos0 += e01;
            if (l0 == lr1) pos1 += e10;
            if (l1 == lr1) pos1 += e11;
        }
        __syncthreads();
        if (c + 2 < nch) load_chunk(c + 2, buf);
    }

    // reduce across the 4 lanes of each quad (same g -> same rows)
#pragma unroll
    for (int off = 1; off <= 2; off <<= 1) {
        all0 += __shfl_xor_sync(0xffffffffu, all0, off);
        all1 += __shfl_xor_sync(0xffffffffu, all1, off);
        pos0 += __shfl_xor_sync(0xffffffffu, pos0, off);
        pos1 += __shfl_xor_sync(0xffffffffu, pos1, off);
    }
    if (t == 0) {
        g_all[rb + g] = all0;     g_pos[rb + g] = pos0;
        g_all[rb + g + 8] = all1; g_pos[rb + g + 8] = pos1;
    }
}

// ------------------------------------------------------------------ K2 ------
__global__ void k_rowloss(int n) {
    int row = blockIdx.x * blockDim.x + threadIdx.x;
    float li = 0.f;
    int v = 0;
    if (row < n) {
        const __nv_bfloat16* a = g_As + (size_t)row * DIM;
        const __nv_bfloat16* b = g_Bb + (size_t)row * DIM;
        float s = 0.f;
#pragma unroll
        for (int i = 0; i < DIM; ++i)
            s += __bfloat162float(a[i]) * __bfloat162float(b[i]);
        float es  = ex2f(s);                 // same product the MMA diagonal computed
        float pos = g_pos[row] - es;
        float all = g_all[row] - es;
        v = (g_cnt[g_lab[row]] > 1) ? 1 : 0;
        if (v) li = logf(all) - logf(pos);   // = -(log pos - log all)
    }
    __shared__ float ssum[256];
    __shared__ int   scnt[256];
    ssum[threadIdx.x] = li;
    scnt[threadIdx.x] = v;
    __syncthreads();
    for (int o = 128; o > 0; o >>= 1) {
        if (threadIdx.x < o) {
            ssum[threadIdx.x] += ssum[threadIdx.x + o];
            scnt[threadIdx.x] += scnt[threadIdx.x + o];
        }
        __syncthreads();
    }
    if (threadIdx.x == 0) {
        g_bsum[blockIdx.x] = ssum[0];
        g_bcnt[blockIdx.x] = scnt[0];
    }
}

// ------------------------------------------------------------------ K3 ------
__global__ void k_final(float* out, int nb) {
    float s = 0.f;
    int c = 0;
    for (int i = threadIdx.x; i < nb; i += 32) {
        s += g_bsum[i];
        c += g_bcnt[i];
    }
#pragma unroll
    for (int o = 16; o > 0; o >>= 1) {
        s += __shfl_xor_sync(0xffffffffu, s, o);
        c += __shfl_xor_sync(0xffffffffu, c, o);
    }
    if (threadIdx.x == 0) out[0] = (c > 0) ? (s / (float)c) : 0.f;
}

// ----------------------------------------------------------------- launch ---
extern "C" void kernel_launch(void* const* d_in, const int* in_sizes, int n_in,
                              void* d_out, int out_size) {
    const float* emb = (const float*)d_in[0];
    const void*  lab = d_in[1];
    int n = in_sizes[1];                       // 16384

    k_zero<<<1, 64>>>((const int*)lab);
    k_convert<<<(n + 255) / 256, 256>>>(emb, lab, n);
    k_main<<<n / BM, 256>>>(n);
    int nb2 = (n + 255) / 256;                 // 64
    k_rowloss<<<nb2, 256>>>(n);
    k_final<<<1, 32>>>((float*)d_out, nb2);
}